// round 15
// baseline (speedup 1.0000x reference)
#include <cuda_runtime.h>
#include <math.h>
#include <stdint.h>

#define NB    64
#define CCH   128
#define HH    56
#define WWW   56
#define HWSZ  (HH * WWW)
#define CHW   (CCH * HWSZ)
#define TOTAL (NB * CHW)
#define WELEM (CCH * CCH * 9)
#define NHW   (NB * HWSZ)

__device__ float         g_buf1[TOTAL];       // conv1 out, then conv2 out (fp32 NCHW)
__device__ unsigned char g_act8[TOTAL];       // act1 codes 0..15, NHWC [n][p][ci]
__device__ float         g_wq1[WELEM];        // quantized w1 fp32, [k=ci*9+kk][co]
__device__ signed char   g_w2s8[9 * 128 * 128]; // w2 codes s8 [kk][co][ci]
__device__ float         g_wq2f[WELEM];       // w2 integer codes as fp32, [k][co]
__device__ float         g_wmax[2];
__device__ float         g_mean[2 * CCH];
__device__ float         g_istd[2 * CCH];
__device__ double        g_ps[CCH * 16];
__device__ double        g_pq[CCH * 16];

// packed fp32x2 FMA (SASS FFMA2)
__device__ __forceinline__ void fma_f32x2(unsigned long long& d,
                                          unsigned long long a, unsigned long long b) {
    asm("fma.rn.f32x2 %0, %1, %2, %0;" : "+l"(d) : "l"(a), "l"(b));
}
// duplicate one f32 into a packed (v,v) register pair — ALU pipe
__device__ __forceinline__ unsigned long long dup2(float v) {
    unsigned long long d;
    asm("mov.b64 %0, {%1, %1};" : "=l"(d) : "f"(v));
    return d;
}
// warp mma: D(16x8,s32) += A(16x32,s8,row) * B(32x8,s8,col)
__device__ __forceinline__ void mma16832(int* c, uint32_t a0, uint32_t a1,
                                         uint32_t a2, uint32_t a3,
                                         uint32_t b0, uint32_t b1) {
    asm("mma.sync.aligned.m16n8k32.row.col.s32.s8.s8.s32 "
        "{%0,%1,%2,%3},{%4,%5,%6,%7},{%8,%9},{%0,%1,%2,%3};"
        : "+r"(c[0]), "+r"(c[1]), "+r"(c[2]), "+r"(c[3])
        : "r"(a0), "r"(a1), "r"(a2), "r"(a3), "r"(b0), "r"(b1));
}

// ---- no-op probe: keeps the harness's fixed ncu skip aligned on k_conv1
__global__ void k_probe() {}

// ---- prologue --------------------------------------------------------------
__global__ void k_wmax(const float* __restrict__ w1, const float* __restrict__ w2) {
    const float* w = (blockIdx.x == 0) ? w1 : w2;
    __shared__ float sm[1024];
    float m = 0.0f;
    for (int i = threadIdx.x; i < WELEM; i += 1024)
        m = fmaxf(m, fabsf((float)tanh((double)w[i])));
    sm[threadIdx.x] = m; __syncthreads();
    for (int o = 512; o > 0; o >>= 1) {
        if (threadIdx.x < o) sm[threadIdx.x] = fmaxf(sm[threadIdx.x], sm[threadIdx.x + o]);
        __syncthreads();
    }
    if (threadIdx.x == 0) g_wmax[blockIdx.x] = sm[0];
}

__global__ void k_wquant(const float* __restrict__ w1, const float* __restrict__ w2) {
    int i = blockIdx.x * 256 + threadIdx.x;
    if (i >= WELEM) return;
    const float* w = (blockIdx.y == 0) ? w1 : w2;
    float M  = g_wmax[blockIdx.y];
    float wt = (float)tanh((double)w[i]);
    float wn = wt / (2.0f * M) + 0.5f;
    float rr = rintf(wn * 15.0f);
    int co = i / 1152, rem = i - co * 1152;       // rem = ci*9 + kk
    if (blockIdx.y == 0) {
        float qq = rr / 15.0f;
        float quant = wn + (qq - wn);
        g_wq1[rem * CCH + co] = 2.0f * quant - 1.0f;
    } else {
        int ci = rem / 9, kk = rem - ci * 9;
        int wi = (int)(2.0f * rr) - 15;           // odd int in [-15,15]
        g_w2s8[(kk * 128 + co) * 128 + ci] = (signed char)wi;
        g_wq2f[rem * CCH + co] = (float)wi;       // same codes, fp32
    }
}

// ---- conv1: FFMA2, 8co x 8px per thread (round-14, best so far) -----------
__global__ void __launch_bounds__(128) k_conv1(const float* __restrict__ in)
{
    __shared__ float sIn[8][10][10];   // 3.2 KB
    __shared__ float sW[72][128];      // 36.9 KB

    const int t = threadIdx.x, tx = t & 15, r = t >> 4;
    const int w0 = blockIdx.x * 8, h0 = blockIdx.y * 8;
    const int n = blockIdx.z;
    const float* inN = in + (size_t)n * CHW;
    unsigned long long acc[4][8] = {};   // [co-pair][px]

    #pragma unroll 1
    for (int ci0 = 0; ci0 < CCH; ci0 += 8) {
        for (int i = t; i < 800; i += 128) {
            int ci = i / 100, rem = i - ci * 100;
            int rr = rem / 10, cc = rem - rr * 10;
            int h = h0 + rr - 1, w = w0 + cc - 1;
            float v = 0.0f;
            if ((unsigned)h < 56u && (unsigned)w < 56u)
                v = inN[(ci0 + ci) * HWSZ + h * WWW + w];
            ((float*)sIn)[i] = v;
        }
        for (int i = t; i < 2304; i += 128) {       // 72 rows x 32 float4
            int r4 = i >> 5, cq = i & 31;
            int ci = r4 / 9, kk = r4 - ci * 9;
            *(float4*)&sW[r4][cq * 4] =
                *(const float4*)&g_wq1[((ci0 + ci) * 9 + kk) * CCH + cq * 4];
        }
        __syncthreads();

        #pragma unroll 1
        for (int ci = 0; ci < 8; ci++) {
            #pragma unroll
            for (int ky = 0; ky < 3; ky++) {
                unsigned long long a[10];
                #pragma unroll
                for (int q = 0; q < 10; q++) a[q] = dup2(sIn[ci][r + ky][q]);
                #pragma unroll
                for (int kx = 0; kx < 3; kx++) {
                    const float* wr = &sW[ci * 9 + ky * 3 + kx][tx * 8];
                    unsigned long long w01 = *(const unsigned long long*)wr;
                    unsigned long long w23 = *(const unsigned long long*)(wr + 2);
                    unsigned long long w45 = *(const unsigned long long*)(wr + 4);
                    unsigned long long w67 = *(const unsigned long long*)(wr + 6);
                    #pragma unroll
                    for (int j = 0; j < 8; j++) {
                        fma_f32x2(acc[0][j], w01, a[kx + j]);
                        fma_f32x2(acc[1][j], w23, a[kx + j]);
                        fma_f32x2(acc[2][j], w45, a[kx + j]);
                        fma_f32x2(acc[3][j], w67, a[kx + j]);
                    }
                }
            }
        }
        __syncthreads();
    }

    #pragma unroll
    for (int p = 0; p < 4; p++) {
        float lo[8], hi[8];
        #pragma unroll
        for (int j = 0; j < 8; j++) {
            float2 v = *(float2*)&acc[p][j];
            lo[j] = v.x; hi[j] = v.y;
        }
        int coL = tx * 8 + 2 * p;
        float* d0 = &g_buf1[((size_t)n * CCH + coL) * HWSZ + (h0 + r) * WWW + w0];
        float* d1 = &g_buf1[((size_t)n * CCH + coL + 1) * HWSZ + (h0 + r) * WWW + w0];
        *(float4*)d0       = make_float4(lo[0], lo[1], lo[2], lo[3]);
        *(float4*)(d0 + 4) = make_float4(lo[4], lo[5], lo[6], lo[7]);
        *(float4*)d1       = make_float4(hi[0], hi[1], hi[2], hi[3]);
        *(float4*)(d1 + 4) = make_float4(hi[4], hi[5], hi[6], hi[7]);
    }
}

// ---- conv2 hybrid: s8 mma (images 0..35) + FFMA2 (images 36..63) ----------
// Both paths 256 threads, both bit-exact (integer products exact in s32/fp32,
// same final *1/225f rounding). Interleaved by bid%92 so each SM co-hosts
// one mma CTA + one FFMA2 CTA (2 x 111KB smem fits) -> both pipes busy.
#define SMW8_STRIDE 144
#define SMW8_BYTES  (9 * 64 * 144)     // 82944
#define SMA8_OFF    SMW8_BYTES
#define SMA8_IMG    (100 * 144)        // 14400
#define SM2TOT      (SMW8_BYTES + 2 * SMA8_IMG)  // 111744

__global__ void __launch_bounds__(256) k_conv2hy()
{
    extern __shared__ char sm[];
    const int t = threadIdx.x, lane = t & 31, warp = t >> 5;
    const int bid = blockIdx.x;
    const int tile = bid / 92, u = bid % 92;
    const int w0 = (tile % 7) * 8, h0 = (tile / 7) * 8;

    if (u < 36) {
        // ===== MMA path: image pair from 0..35, 64-co half =================
        const int half = u & 1, n0 = (u >> 1) * 2;

        for (int i = t; i < 4608; i += 256) {
            int row = i >> 3, q = i & 7;
            int kk = row >> 6, coL = row & 63;
            int4 v = ((const int4*)g_w2s8)[(kk * 128 + half * 64 + coL) * 8 + q];
            *(int4*)(sm + row * SMW8_STRIDE + q * 16) = v;
        }
        for (int img = 0; img < 2; img++) {
            for (int i = t; i < 800; i += 256) {
                int px = i >> 3, q = i & 7;
                int py = px / 10, pxx = px - py * 10;
                int h = h0 + py - 1, w = w0 + pxx - 1;
                int4 v = make_int4(0, 0, 0, 0);
                if ((unsigned)h < 56u && (unsigned)w < 56u)
                    v = ((const int4*)g_act8)[((n0 + img) * HWSZ + h * WWW + w) * 8 + q];
                *(int4*)(sm + SMA8_OFF + img * SMA8_IMG + py * 1440 + pxx * 144 + q * 16) = v;
            }
        }
        __syncthreads();

        const int mtp = warp & 3, cog = warp >> 2;
        const int colq = lane >> 2, kq = (lane & 3) * 4;
        int c[2][4][4] = {};

        #pragma unroll 1
        for (int kk = 0; kk < 9; kk++) {
            const int ky = kk / 3, kx = kk - ky * 3;
            #pragma unroll
            for (int ck = 0; ck < 4; ck++) {
                uint32_t b[4][2];
                #pragma unroll
                for (int nt = 0; nt < 4; nt++) {
                    const char* p = sm + (kk * 64 + cog * 32 + nt * 8 + colq) * SMW8_STRIDE
                                  + ck * 32 + kq;
                    b[nt][0] = *(const uint32_t*)p;
                    b[nt][1] = *(const uint32_t*)(p + 16);
                }
                #pragma unroll
                for (int img = 0; img < 2; img++) {
                    const char* p = sm + SMA8_OFF + img * SMA8_IMG
                                  + (mtp * 2 + ky) * 1440 + (colq + kx) * 144 + ck * 32 + kq;
                    uint32_t a0 = *(const uint32_t*)p;
                    uint32_t a1 = *(const uint32_t*)(p + 1440);
                    uint32_t a2 = *(const uint32_t*)(p + 16);
                    uint32_t a3 = *(const uint32_t*)(p + 1456);
                    #pragma unroll
                    for (int nt = 0; nt < 4; nt++)
                        mma16832(c[img][nt], a0, a1, a2, a3, b[nt][0], b[nt][1]);
                }
            }
        }

        const float sc = 1.0f / 225.0f;
        const int m = lane >> 2, nb = (lane & 3) * 2;
        const int h = h0 + mtp * 2, w = w0 + m;
        #pragma unroll
        for (int img = 0; img < 2; img++) {
            #pragma unroll
            for (int nt = 0; nt < 4; nt++) {
                int co = half * 64 + cog * 32 + nt * 8 + nb;
                size_t base = ((size_t)(n0 + img) * CCH + co) * HWSZ;
                const int* cf = c[img][nt];
                g_buf1[base + h * WWW + w]              = (float)cf[0] * sc;
                g_buf1[base + HWSZ + h * WWW + w]       = (float)cf[1] * sc;
                g_buf1[base + (h + 1) * WWW + w]        = (float)cf[2] * sc;
                g_buf1[base + HWSZ + (h + 1) * WWW + w] = (float)cf[3] * sc;
            }
        }
    } else {
        // ===== FFMA2 path: one image from 36..63, 64-co half ===============
        const int f = u - 36;                       // 0..55
        const int n = 36 + (f >> 1), coBase = (f & 1) * 64;

        float2* sIn = (float2*)sm;                  // [8 ci][100 px] dup pairs
        float*  sW  = (float*)(sm + 8 * 100 * 8);   // [72][64]

        const int tx = t & 15, ty = t >> 4;
        const int r = ty >> 1, c0 = (ty & 1) * 4;
        unsigned long long acc[2][4] = {};          // [co-pair][px]

        #pragma unroll 1
        for (int ci0 = 0; ci0 < CCH; ci0 += 8) {
            if (t < 100) {
                int rr = t / 10, cc = t - rr * 10;
                int h = h0 + rr - 1, w = w0 + cc - 1;
                unsigned long long v8 = 0;
                if ((unsigned)h < 56u && (unsigned)w < 56u)
                    v8 = *(const unsigned long long*)
                         &g_act8[((size_t)(n * HWSZ + h * WWW + w)) * 128 + ci0];
                #pragma unroll
                for (int b = 0; b < 8; b++) {
                    float fv = (float)(int)((v8 >> (8 * b)) & 255);
                    sIn[b * 100 + t] = make_float2(fv, fv);
                }
            }
            for (int i = t; i < 1152; i += 256) {
                int r4 = i >> 4, cq = i & 15;
                *(float4*)&sW[r4 * 64 + cq * 4] =
                    *(const float4*)&g_wq2f[(ci0 * 9 + r4) * CCH + coBase + cq * 4];
            }
            __syncthreads();

            #pragma unroll 1
            for (int ci = 0; ci < 8; ci++) {
                #pragma unroll
                for (int ky = 0; ky < 3; ky++) {
                    unsigned long long a[6];
                    #pragma unroll
                    for (int q = 0; q < 6; q++)
                        a[q] = *(const unsigned long long*)
                               &sIn[ci * 100 + (r + ky) * 10 + c0 + q];
                    #pragma unroll
                    for (int kx = 0; kx < 3; kx++) {
                        const float* wr = &sW[(ci * 9 + ky * 3 + kx) * 64 + tx * 4];
                        unsigned long long w01 = *(const unsigned long long*)wr;
                        unsigned long long w23 = *(const unsigned long long*)(wr + 2);
                        #pragma unroll
                        for (int j = 0; j < 4; j++) {
                            fma_f32x2(acc[0][j], w01, a[kx + j]);
                            fma_f32x2(acc[1][j], w23, a[kx + j]);
                        }
                    }
                }
            }
            __syncthreads();
        }

        const float sc = 1.0f / 225.0f;
        #pragma unroll
        for (int p = 0; p < 2; p++) {
            float lo[4], hi[4];
            #pragma unroll
            for (int j = 0; j < 4; j++) {
                float2 v = *(float2*)&acc[p][j];
                lo[j] = v.x * sc; hi[j] = v.y * sc;
            }
            int coL = coBase + tx * 4 + 2 * p;
            *(float4*)&g_buf1[((size_t)n * CCH + coL) * HWSZ + (h0 + r) * WWW + w0 + c0] =
                make_float4(lo[0], lo[1], lo[2], lo[3]);
            *(float4*)&g_buf1[((size_t)n * CCH + coL + 1) * HWSZ + (h0 + r) * WWW + w0 + c0] =
                make_float4(hi[0], hi[1], hi[2], hi[3]);
        }
    }
}

// ---- stats ----------------------------------------------------------------
__global__ void k_statsA() {
    const int c = blockIdx.x, j = blockIdx.y, t = threadIdx.x;
    const size_t base = (size_t)(4 * j) * CHW + (size_t)c * HWSZ;
    float s = 0.f, cs = 0.f, q = 0.f, cq = 0.f;
    for (int idx = t; idx < 4 * HWSZ; idx += 256) {
        int n = idx / HWSZ, p = idx - n * HWSZ;
        float v = g_buf1[base + (size_t)n * CHW + p];
        float y1 = v - cs, t1 = s + y1; cs = (t1 - s) - y1; s = t1;
        float v2 = v * v;
        float y2 = v2 - cq, t2 = q + y2; cq = (t2 - q) - y2; q = t2;
    }
    __shared__ double ss[256], sq[256];
    ss[t] = (double)s; sq[t] = (double)q;
    __syncthreads();
    for (int o = 128; o > 0; o >>= 1) {
        if (t < o) { ss[t] += ss[t + o]; sq[t] += sq[t + o]; }
        __syncthreads();
    }
    if (t == 0) { g_ps[c * 16 + j] = ss[0]; g_pq[c * 16 + j] = sq[0]; }
}

__global__ void k_statsB(int pass) {
    int c = threadIdx.x;
    double s = 0.0, q = 0.0;
    for (int j = 0; j < 16; j++) { s += g_ps[c * 16 + j]; q += g_pq[c * 16 + j]; }
    double m = s / (double)NHW;
    double var = q / (double)NHW - m * m;
    g_mean[pass * CCH + c] = (float)m;
    g_istd[pass * CCH + c] = (float)(1.0 / sqrt(var + 1e-5));
}

// ---- BN1 + act -> NHWC s8 codes -------------------------------------------
__global__ void __launch_bounds__(256) k_bnact8(const float* __restrict__ gamma,
                                                const float* __restrict__ beta) {
    __shared__ unsigned char s8[128 * 58];
    int n = blockIdx.x / HH, h = blockIdx.x % HH;
    int t = threadIdx.x;
    for (int idx = t; idx < 128 * 56; idx += 256) {
        int c = idx / 56, p = idx - c * 56;
        float v = (g_buf1[(size_t)n * CHW + (size_t)c * HWSZ + h * WWW + p]
                   - g_mean[c]) * g_istd[c];
        v = v * gamma[c] + beta[c];
        float xc = fminf(fmaxf(v, 0.0f), 1.0f);
        s8[c * 58 + p] = (unsigned char)(int)rintf(xc * 15.0f);  // 0..15
    }
    __syncthreads();
    for (int j = t; j < 56 * 8; j += 256) {
        int p = j >> 3, g = j & 7;
        uint32_t wrd[4];
        #pragma unroll
        for (int q = 0; q < 4; q++) {
            uint32_t acc = 0;
            #pragma unroll
            for (int b = 0; b < 4; b++)
                acc |= (uint32_t)s8[(g * 16 + q * 4 + b) * 58 + p] << (8 * b);
            wrd[q] = acc;
        }
        uint4 v = make_uint4(wrd[0], wrd[1], wrd[2], wrd[3]);
        ((uint4*)g_act8)[((size_t)(n * HWSZ + h * WWW + p)) * 8 + g] = v;
    }
}

// ---- BN2 + residual + act -> out ------------------------------------------
__global__ void k_final(const float* __restrict__ x,
                        const float* __restrict__ gamma, const float* __restrict__ beta,
                        float* __restrict__ out) {
    int i = blockIdx.x * 256 + threadIdx.x;
    int c = (i / HWSZ) & (CCH - 1);
    float xn = (g_buf1[i] - g_mean[CCH + c]) * g_istd[CCH + c];
    float v  = xn * gamma[c] + beta[c] + x[i];
    float xc = fminf(fmaxf(v, 0.0f), 1.0f);
    float qq = rintf(xc * 15.0f) / 15.0f;
    out[i] = xc + (qq - xc);
}

// ---------------------------------------------------------------------------
extern "C" void kernel_launch(void* const* d_in, const int* in_sizes, int n_in,
                              void* d_out, int out_size)
{
    const float* x  = (const float*)d_in[0];
    const float* w1 = (const float*)d_in[1];
    const float* w2 = (const float*)d_in[2];
    const float* g1 = (const float*)d_in[3];
    const float* b1 = (const float*)d_in[4];
    const float* g2 = (const float*)d_in[5];
    const float* b2 = (const float*)d_in[6];
    float* out = (float*)d_out;

    cudaFuncSetAttribute(k_conv2hy, cudaFuncAttributeMaxDynamicSharedMemorySize, SM2TOT);

    k_wmax<<<2, 1024>>>(w1, w2);
    k_wquant<<<dim3(576, 2), 256>>>(w1, w2);
    k_probe<<<1, 32>>>();                               // aligns ncu capture on k_conv1

    k_conv1<<<dim3(7, 7, NB), 128>>>(x);                // conv1 -> g_buf1
    k_statsA<<<dim3(CCH, 16), 256>>>();
    k_statsB<<<1, CCH>>>(0);
    k_bnact8<<<NB * HH, 256>>>(g1, b1);                 // -> g_act8 (NHWC s8)
    k_conv2hy<<<49 * 92, 256, SM2TOT>>>();              // hybrid mma+FFMA2 conv2
    k_statsA<<<dim3(CCH, 16), 256>>>();
    k_statsB<<<1, CCH>>>(1);
    k_final<<<TOTAL / 256, 256>>>(x, g2, b2, out);
}

// round 16
// speedup vs baseline: 1.1748x; 1.1748x over previous
#include <cuda_runtime.h>
#include <math.h>
#include <stdint.h>

#define NB    64
#define CCH   128
#define HH    56
#define WWW   56
#define HWSZ  (HH * WWW)
#define CHW   (CCH * HWSZ)
#define TOTAL (NB * CHW)
#define WELEM (CCH * CCH * 9)
#define NHW   (NB * HWSZ)

__device__ float         g_buf1[TOTAL];       // conv1 out, then conv2 out (fp32 NCHW)
__device__ unsigned char g_act8[TOTAL];       // act1 codes 0..15, NHWC [n][p][ci]
__device__ float         g_wq1[WELEM];        // quantized w1 fp32, [k=ci*9+kk][co]
__device__ signed char   g_w2s8[9 * 128 * 128]; // w2 codes s8 [kk][co][ci]
__device__ float         g_wmax[2];
__device__ float         g_mean[2 * CCH];
__device__ float         g_istd[2 * CCH];
__device__ double        g_ps[CCH * 16];
__device__ double        g_pq[CCH * 16];

// packed fp32x2 FMA (SASS FFMA2)
__device__ __forceinline__ void fma_f32x2(unsigned long long& d,
                                          unsigned long long a, unsigned long long b) {
    asm("fma.rn.f32x2 %0, %1, %2, %0;" : "+l"(d) : "l"(a), "l"(b));
}
// duplicate one f32 into a packed (v,v) register pair — ALU pipe
__device__ __forceinline__ unsigned long long dup2(float v) {
    unsigned long long d;
    asm("mov.b64 %0, {%1, %1};" : "=l"(d) : "f"(v));
    return d;
}
// warp mma: D(16x8,s32) += A(16x32,s8,row) * B(32x8,s8,col)
__device__ __forceinline__ void mma16832(int* c, uint32_t a0, uint32_t a1,
                                         uint32_t a2, uint32_t a3,
                                         uint32_t b0, uint32_t b1) {
    asm("mma.sync.aligned.m16n8k32.row.col.s32.s8.s8.s32 "
        "{%0,%1,%2,%3},{%4,%5,%6,%7},{%8,%9},{%0,%1,%2,%3};"
        : "+r"(c[0]), "+r"(c[1]), "+r"(c[2]), "+r"(c[3])
        : "r"(a0), "r"(a1), "r"(a2), "r"(a3), "r"(b0), "r"(b1));
}

// ---- no-op probe: keeps the harness's fixed ncu skip aligned on k_conv1
__global__ void k_probe() {}

// ---- prologue --------------------------------------------------------------
__global__ void k_wmax(const float* __restrict__ w1, const float* __restrict__ w2) {
    const float* w = (blockIdx.x == 0) ? w1 : w2;
    __shared__ float sm[1024];
    float m = 0.0f;
    for (int i = threadIdx.x; i < WELEM; i += 1024)
        m = fmaxf(m, fabsf((float)tanh((double)w[i])));
    sm[threadIdx.x] = m; __syncthreads();
    for (int o = 512; o > 0; o >>= 1) {
        if (threadIdx.x < o) sm[threadIdx.x] = fmaxf(sm[threadIdx.x], sm[threadIdx.x + o]);
        __syncthreads();
    }
    if (threadIdx.x == 0) g_wmax[blockIdx.x] = sm[0];
}

__global__ void k_wquant(const float* __restrict__ w1, const float* __restrict__ w2) {
    int i = blockIdx.x * 256 + threadIdx.x;
    if (i >= WELEM) return;
    const float* w = (blockIdx.y == 0) ? w1 : w2;
    float M  = g_wmax[blockIdx.y];
    float wt = (float)tanh((double)w[i]);
    float wn = wt / (2.0f * M) + 0.5f;
    float rr = rintf(wn * 15.0f);
    int co = i / 1152, rem = i - co * 1152;       // rem = ci*9 + kk
    if (blockIdx.y == 0) {
        float qq = rr / 15.0f;
        float quant = wn + (qq - wn);
        g_wq1[rem * CCH + co] = 2.0f * quant - 1.0f;
    } else {
        int ci = rem / 9, kk = rem - ci * 9;
        int wi = (int)(2.0f * rr) - 15;           // odd int in [-15,15]
        g_w2s8[(kk * 128 + co) * 128 + ci] = (signed char)wi;
    }
}

// ---- conv1: FFMA2, 8co x 8px per thread, slot-lean loads ------------------
// 128 threads: tx = t&15 (8-co group), r = t>>4 (row). Weights via LDS.128
// (ulonglong2: packed pairs feed FFMA2 directly); inputs via LDS.64 float2
// + ALU dup2. Arithmetic order unchanged from round 14 (bit-exact).
__global__ void __launch_bounds__(128) k_conv1(const float* __restrict__ in)
{
    __shared__ float sIn[8][10][10];   // 3.2 KB
    __shared__ float sW[72][128];      // 36.9 KB

    const int t = threadIdx.x, tx = t & 15, r = t >> 4;
    const int w0 = blockIdx.x * 8, h0 = blockIdx.y * 8;
    const int n = blockIdx.z;
    const float* inN = in + (size_t)n * CHW;
    unsigned long long acc[4][8] = {};   // [co-pair][px]

    #pragma unroll 1
    for (int ci0 = 0; ci0 < CCH; ci0 += 8) {
        for (int i = t; i < 800; i += 128) {
            int ci = i / 100, rem = i - ci * 100;
            int rr = rem / 10, cc = rem - rr * 10;
            int h = h0 + rr - 1, w = w0 + cc - 1;
            float v = 0.0f;
            if ((unsigned)h < 56u && (unsigned)w < 56u)
                v = inN[(ci0 + ci) * HWSZ + h * WWW + w];
            ((float*)sIn)[i] = v;
        }
        for (int i = t; i < 2304; i += 128) {       // 72 rows x 32 float4
            int r4 = i >> 5, cq = i & 31;
            int ci = r4 / 9, kk = r4 - ci * 9;
            *(float4*)&sW[r4][cq * 4] =
                *(const float4*)&g_wq1[((ci0 + ci) * 9 + kk) * CCH + cq * 4];
        }
        __syncthreads();

        #pragma unroll 1
        for (int ci = 0; ci < 8; ci++) {
            #pragma unroll
            for (int ky = 0; ky < 3; ky++) {
                unsigned long long a[10];
                #pragma unroll
                for (int q = 0; q < 10; q += 2) {
                    float2 p = *(const float2*)&sIn[ci][r + ky][q];  // LDS.64
                    a[q]     = dup2(p.x);
                    a[q + 1] = dup2(p.y);
                }
                #pragma unroll
                for (int kx = 0; kx < 3; kx++) {
                    const ulonglong2* wr =
                        (const ulonglong2*)&sW[ci * 9 + ky * 3 + kx][tx * 8];
                    ulonglong2 wA = wr[0];          // LDS.128: (w01, w23)
                    ulonglong2 wB = wr[1];          // LDS.128: (w45, w67)
                    #pragma unroll
                    for (int j = 0; j < 8; j++) {
                        fma_f32x2(acc[0][j], wA.x, a[kx + j]);
                        fma_f32x2(acc[1][j], wA.y, a[kx + j]);
                        fma_f32x2(acc[2][j], wB.x, a[kx + j]);
                        fma_f32x2(acc[3][j], wB.y, a[kx + j]);
                    }
                }
            }
        }
        __syncthreads();
    }

    #pragma unroll
    for (int p = 0; p < 4; p++) {
        float lo[8], hi[8];
        #pragma unroll
        for (int j = 0; j < 8; j++) {
            float2 v = *(float2*)&acc[p][j];
            lo[j] = v.x; hi[j] = v.y;
        }
        int coL = tx * 8 + 2 * p;
        float* d0 = &g_buf1[((size_t)n * CCH + coL) * HWSZ + (h0 + r) * WWW + w0];
        float* d1 = &g_buf1[((size_t)n * CCH + coL + 1) * HWSZ + (h0 + r) * WWW + w0];
        *(float4*)d0       = make_float4(lo[0], lo[1], lo[2], lo[3]);
        *(float4*)(d0 + 4) = make_float4(lo[4], lo[5], lo[6], lo[7]);
        *(float4*)d1       = make_float4(hi[0], hi[1], hi[2], hi[3]);
        *(float4*)(d1 + 4) = make_float4(hi[4], hi[5], hi[6], hi[7]);
    }
}

// ---- conv2: warp mma.sync s8 (m16n8k32), exact integer arithmetic ---------
#define SMW8_STRIDE 144
#define SMW8_BYTES  (9 * 64 * 144)     // 82944
#define SMA8_OFF    SMW8_BYTES
#define SMA8_IMG    (100 * 144)        // 14400
#define SM2TOT      (SMW8_BYTES + 2 * SMA8_IMG)  // 111744

__global__ void __launch_bounds__(256) k_conv2s()
{
    extern __shared__ char sm[];
    const int t = threadIdx.x, lane = t & 31, warp = t >> 5;
    const int w0 = blockIdx.x * 8, h0 = blockIdx.y * 8;
    const int half = blockIdx.z & 1, n0 = (blockIdx.z >> 1) * 2;

    for (int i = t; i < 4608; i += 256) {
        int row = i >> 3, u = i & 7;
        int kk = row >> 6, coL = row & 63;
        int4 v = ((const int4*)g_w2s8)[(kk * 128 + half * 64 + coL) * 8 + u];
        *(int4*)(sm + row * SMW8_STRIDE + u * 16) = v;
    }
    for (int img = 0; img < 2; img++) {
        for (int i = t; i < 800; i += 256) {
            int px = i >> 3, u = i & 7;
            int py = px / 10, pxx = px - py * 10;
            int h = h0 + py - 1, w = w0 + pxx - 1;
            int4 v = make_int4(0, 0, 0, 0);
            if ((unsigned)h < 56u && (unsigned)w < 56u)
                v = ((const int4*)g_act8)[((n0 + img) * HWSZ + h * WWW + w) * 8 + u];
            *(int4*)(sm + SMA8_OFF + img * SMA8_IMG + py * 1440 + pxx * 144 + u * 16) = v;
        }
    }
    __syncthreads();

    const int mtp  = warp & 3;
    const int cog  = warp >> 2;
    const int colq = lane >> 2;
    const int kq   = (lane & 3) * 4;
    int c[2][4][4] = {};

    #pragma unroll 1
    for (int kk = 0; kk < 9; kk++) {
        const int ky = kk / 3, kx = kk - ky * 3;
        #pragma unroll
        for (int ck = 0; ck < 4; ck++) {
            uint32_t b[4][2];
            #pragma unroll
            for (int nt = 0; nt < 4; nt++) {
                const char* p = sm + (kk * 64 + cog * 32 + nt * 8 + colq) * SMW8_STRIDE
                              + ck * 32 + kq;
                b[nt][0] = *(const uint32_t*)p;
                b[nt][1] = *(const uint32_t*)(p + 16);
            }
            #pragma unroll
            for (int img = 0; img < 2; img++) {
                const char* p = sm + SMA8_OFF + img * SMA8_IMG
                              + (mtp * 2 + ky) * 1440
                              + (colq + kx) * 144 + ck * 32 + kq;
                uint32_t a0 = *(const uint32_t*)p;
                uint32_t a1 = *(const uint32_t*)(p + 1440);
                uint32_t a2 = *(const uint32_t*)(p + 16);
                uint32_t a3 = *(const uint32_t*)(p + 1456);
                #pragma unroll
                for (int nt = 0; nt < 4; nt++)
                    mma16832(c[img][nt], a0, a1, a2, a3, b[nt][0], b[nt][1]);
            }
        }
    }

    const float sc = 1.0f / 225.0f;
    const int m = lane >> 2, nb = (lane & 3) * 2;
    const int h = h0 + mtp * 2, w = w0 + m;
    #pragma unroll
    for (int img = 0; img < 2; img++) {
        #pragma unroll
        for (int nt = 0; nt < 4; nt++) {
            int co = half * 64 + cog * 32 + nt * 8 + nb;
            size_t base = ((size_t)(n0 + img) * CCH + co) * HWSZ;
            const int* cf = c[img][nt];
            g_buf1[base + h * WWW + w]               = (float)cf[0] * sc;
            g_buf1[base + HWSZ + h * WWW + w]        = (float)cf[1] * sc;
            g_buf1[base + (h + 1) * WWW + w]         = (float)cf[2] * sc;
            g_buf1[base + HWSZ + (h + 1) * WWW + w]  = (float)cf[3] * sc;
        }
    }
}

// ---- stats ----------------------------------------------------------------
__global__ void k_statsA() {
    const int c = blockIdx.x, j = blockIdx.y, t = threadIdx.x;
    const size_t base = (size_t)(4 * j) * CHW + (size_t)c * HWSZ;
    float s = 0.f, cs = 0.f, q = 0.f, cq = 0.f;
    for (int idx = t; idx < 4 * HWSZ; idx += 256) {
        int n = idx / HWSZ, p = idx - n * HWSZ;
        float v = g_buf1[base + (size_t)n * CHW + p];
        float y1 = v - cs, t1 = s + y1; cs = (t1 - s) - y1; s = t1;
        float v2 = v * v;
        float y2 = v2 - cq, t2 = q + y2; cq = (t2 - q) - y2; q = t2;
    }
    __shared__ double ss[256], sq[256];
    ss[t] = (double)s; sq[t] = (double)q;
    __syncthreads();
    for (int o = 128; o > 0; o >>= 1) {
        if (t < o) { ss[t] += ss[t + o]; sq[t] += sq[t + o]; }
        __syncthreads();
    }
    if (t == 0) { g_ps[c * 16 + j] = ss[0]; g_pq[c * 16 + j] = sq[0]; }
}

__global__ void k_statsB(int pass) {
    int c = threadIdx.x;
    double s = 0.0, q = 0.0;
    for (int j = 0; j < 16; j++) { s += g_ps[c * 16 + j]; q += g_pq[c * 16 + j]; }
    double m = s / (double)NHW;
    double var = q / (double)NHW - m * m;
    g_mean[pass * CCH + c] = (float)m;
    g_istd[pass * CCH + c] = (float)(1.0 / sqrt(var + 1e-5));
}

// ---- BN1 + act -> NHWC s8 codes -------------------------------------------
__global__ void __launch_bounds__(256) k_bnact8(const float* __restrict__ gamma,
                                                const float* __restrict__ beta) {
    __shared__ unsigned char s8[128 * 58];
    int n = blockIdx.x / HH, h = blockIdx.x % HH;
    int t = threadIdx.x;
    for (int idx = t; idx < 128 * 56; idx += 256) {
        int c = idx / 56, p = idx - c * 56;
        float v = (g_buf1[(size_t)n * CHW + (size_t)c * HWSZ + h * WWW + p]
                   - g_mean[c]) * g_istd[c];
        v = v * gamma[c] + beta[c];
        float xc = fminf(fmaxf(v, 0.0f), 1.0f);
        s8[c * 58 + p] = (unsigned char)(int)rintf(xc * 15.0f);  // 0..15
    }
    __syncthreads();
    for (int j = t; j < 56 * 8; j += 256) {
        int p = j >> 3, g = j & 7;
        uint32_t wrd[4];
        #pragma unroll
        for (int q = 0; q < 4; q++) {
            uint32_t acc = 0;
            #pragma unroll
            for (int b = 0; b < 4; b++)
                acc |= (uint32_t)s8[(g * 16 + q * 4 + b) * 58 + p] << (8 * b);
            wrd[q] = acc;
        }
        uint4 v = make_uint4(wrd[0], wrd[1], wrd[2], wrd[3]);
        ((uint4*)g_act8)[((size_t)(n * HWSZ + h * WWW + p)) * 8 + g] = v;
    }
}

// ---- BN2 + residual + act -> out ------------------------------------------
__global__ void k_final(const float* __restrict__ x,
                        const float* __restrict__ gamma, const float* __restrict__ beta,
                        float* __restrict__ out) {
    int i = blockIdx.x * 256 + threadIdx.x;
    int c = (i / HWSZ) & (CCH - 1);
    float xn = (g_buf1[i] - g_mean[CCH + c]) * g_istd[CCH + c];
    float v  = xn * gamma[c] + beta[c] + x[i];
    float xc = fminf(fmaxf(v, 0.0f), 1.0f);
    float qq = rintf(xc * 15.0f) / 15.0f;
    out[i] = xc + (qq - xc);
}

// ---------------------------------------------------------------------------
extern "C" void kernel_launch(void* const* d_in, const int* in_sizes, int n_in,
                              void* d_out, int out_size)
{
    const float* x  = (const float*)d_in[0];
    const float* w1 = (const float*)d_in[1];
    const float* w2 = (const float*)d_in[2];
    const float* g1 = (const float*)d_in[3];
    const float* b1 = (const float*)d_in[4];
    const float* g2 = (const float*)d_in[5];
    const float* b2 = (const float*)d_in[6];
    float* out = (float*)d_out;

    cudaFuncSetAttribute(k_conv2s, cudaFuncAttributeMaxDynamicSharedMemorySize, SM2TOT);

    k_wmax<<<2, 1024>>>(w1, w2);
    k_wquant<<<dim3(576, 2), 256>>>(w1, w2);
    k_probe<<<1, 32>>>();                               // aligns ncu capture on k_conv1

    k_conv1<<<dim3(7, 7, NB), 128>>>(x);                // conv1 -> g_buf1
    k_statsA<<<dim3(CCH, 16), 256>>>();
    k_statsB<<<1, CCH>>>(0);
    k_bnact8<<<NB * HH, 256>>>(g1, b1);                 // -> g_act8 (NHWC s8)
    k_conv2s<<<dim3(7, 7, 64), 256, SM2TOT>>>();        // s8 mma conv2 -> g_buf1
    k_statsA<<<dim3(CCH, 16), 256>>>();
    k_statsB<<<1, CCH>>>(1);
    k_final<<<TOTAL / 256, 256>>>(x, g2, b2, out);
}

// round 17
// speedup vs baseline: 1.6826x; 1.4323x over previous
#include <cuda_runtime.h>
#include <math.h>
#include <stdint.h>

#define NB    64
#define CCH   128
#define HH    56
#define WWW   56
#define HWSZ  (HH * WWW)
#define CHW   (CCH * HWSZ)
#define TOTAL (NB * CHW)
#define WELEM (CCH * CCH * 9)
#define NHW   (NB * HWSZ)

__device__ float         g_buf1[TOTAL];       // conv1 out, then conv2 out (fp32 NCHW)
__device__ unsigned char g_act8[TOTAL];       // act1 codes 0..15, NHWC [n][p][ci]
__device__ float         g_wq1[WELEM];        // quantized w1 fp32, [k=ci*9+kk][co]
__device__ signed char   g_w2s8[9 * 128 * 128]; // w2 codes s8 [kk][co][ci]
__device__ float         g_pmax[2][32];
__device__ float         g_wmax[2];
__device__ float         g_mean[2 * CCH];
__device__ float         g_istd[2 * CCH];
__device__ double        g_ps[CCH * 16];
__device__ double        g_pq[CCH * 16];

// packed fp32x2 FMA (SASS FFMA2)
__device__ __forceinline__ void fma_f32x2(unsigned long long& d,
                                          unsigned long long a, unsigned long long b) {
    asm("fma.rn.f32x2 %0, %1, %2, %0;" : "+l"(d) : "l"(a), "l"(b));
}
// duplicate one f32 into a packed (v,v) register pair — ALU pipe
__device__ __forceinline__ unsigned long long dup2(float v) {
    unsigned long long d;
    asm("mov.b64 %0, {%1, %1};" : "=l"(d) : "f"(v));
    return d;
}
// warp mma: D(16x8,s32) += A(16x32,s8,row) * B(32x8,s8,col)
__device__ __forceinline__ void mma16832(int* c, uint32_t a0, uint32_t a1,
                                         uint32_t a2, uint32_t a3,
                                         uint32_t b0, uint32_t b1) {
    asm("mma.sync.aligned.m16n8k32.row.col.s32.s8.s8.s32 "
        "{%0,%1,%2,%3},{%4,%5,%6,%7},{%8,%9},{%0,%1,%2,%3};"
        : "+r"(c[0]), "+r"(c[1]), "+r"(c[2]), "+r"(c[3])
        : "r"(a0), "r"(a1), "r"(a2), "r"(a3), "r"(b0), "r"(b1));
}

// ---- prologue: two-stage max |tanh(w)| ------------------------------------
__global__ void k_wmaxA(const float* __restrict__ w1, const float* __restrict__ w2) {
    const float* w = (blockIdx.y == 0) ? w1 : w2;
    const int chunk = WELEM / 32;                 // 4608
    const int base = blockIdx.x * chunk;
    __shared__ float sm[256];
    float m = 0.0f;
    for (int i = threadIdx.x; i < chunk; i += 256)
        m = fmaxf(m, fabsf((float)tanh((double)w[base + i])));
    sm[threadIdx.x] = m; __syncthreads();
    for (int o = 128; o > 0; o >>= 1) {
        if (threadIdx.x < o) sm[threadIdx.x] = fmaxf(sm[threadIdx.x], sm[threadIdx.x + o]);
        __syncthreads();
    }
    if (threadIdx.x == 0) g_pmax[blockIdx.y][blockIdx.x] = sm[0];
}
__global__ void k_wmaxB() {
    int tensor = threadIdx.x;                     // 0 or 1
    if (tensor < 2) {
        float m = 0.0f;
        for (int j = 0; j < 32; j++) m = fmaxf(m, g_pmax[tensor][j]);
        g_wmax[tensor] = m;
    }
}

__global__ void k_wquant(const float* __restrict__ w1, const float* __restrict__ w2) {
    int i = blockIdx.x * 256 + threadIdx.x;
    if (i >= WELEM) return;
    const float* w = (blockIdx.y == 0) ? w1 : w2;
    float M  = g_wmax[blockIdx.y];
    float wt = (float)tanh((double)w[i]);
    float wn = wt / (2.0f * M) + 0.5f;
    float rr = rintf(wn * 15.0f);
    int co = i / 1152, rem = i - co * 1152;       // rem = ci*9 + kk
    if (blockIdx.y == 0) {
        float qq = rr / 15.0f;
        float quant = wn + (qq - wn);
        g_wq1[rem * CCH + co] = 2.0f * quant - 1.0f;
    } else {
        int ci = rem / 9, kk = rem - ci * 9;
        int wi = (int)(2.0f * rr) - 15;           // odd int in [-15,15]
        g_w2s8[(kk * 128 + co) * 128 + ci] = (signed char)wi;
    }
}

// ---- conv1: FFMA2, 8co x 8px per thread (round-16 best) -------------------
__global__ void __launch_bounds__(128) k_conv1(const float* __restrict__ in)
{
    __shared__ float sIn[8][10][10];   // 3.2 KB
    __shared__ float sW[72][128];      // 36.9 KB

    const int t = threadIdx.x, tx = t & 15, r = t >> 4;
    const int w0 = blockIdx.x * 8, h0 = blockIdx.y * 8;
    const int n = blockIdx.z;
    const float* inN = in + (size_t)n * CHW;
    unsigned long long acc[4][8] = {};   // [co-pair][px]

    #pragma unroll 1
    for (int ci0 = 0; ci0 < CCH; ci0 += 8) {
        for (int i = t; i < 800; i += 128) {
            int ci = i / 100, rem = i - ci * 100;
            int rr = rem / 10, cc = rem - rr * 10;
            int h = h0 + rr - 1, w = w0 + cc - 1;
            float v = 0.0f;
            if ((unsigned)h < 56u && (unsigned)w < 56u)
                v = inN[(ci0 + ci) * HWSZ + h * WWW + w];
            ((float*)sIn)[i] = v;
        }
        for (int i = t; i < 2304; i += 128) {       // 72 rows x 32 float4
            int r4 = i >> 5, cq = i & 31;
            int ci = r4 / 9, kk = r4 - ci * 9;
            *(float4*)&sW[r4][cq * 4] =
                *(const float4*)&g_wq1[((ci0 + ci) * 9 + kk) * CCH + cq * 4];
        }
        __syncthreads();

        #pragma unroll 1
        for (int ci = 0; ci < 8; ci++) {
            #pragma unroll
            for (int ky = 0; ky < 3; ky++) {
                unsigned long long a[10];
                #pragma unroll
                for (int q = 0; q < 10; q += 2) {
                    float2 p = *(const float2*)&sIn[ci][r + ky][q];  // LDS.64
                    a[q]     = dup2(p.x);
                    a[q + 1] = dup2(p.y);
                }
                #pragma unroll
                for (int kx = 0; kx < 3; kx++) {
                    const ulonglong2* wr =
                        (const ulonglong2*)&sW[ci * 9 + ky * 3 + kx][tx * 8];
                    ulonglong2 wA = wr[0];
                    ulonglong2 wB = wr[1];
                    #pragma unroll
                    for (int j = 0; j < 8; j++) {
                        fma_f32x2(acc[0][j], wA.x, a[kx + j]);
                        fma_f32x2(acc[1][j], wA.y, a[kx + j]);
                        fma_f32x2(acc[2][j], wB.x, a[kx + j]);
                        fma_f32x2(acc[3][j], wB.y, a[kx + j]);
                    }
                }
            }
        }
        __syncthreads();
    }

    #pragma unroll
    for (int p = 0; p < 4; p++) {
        float lo[8], hi[8];
        #pragma unroll
        for (int j = 0; j < 8; j++) {
            float2 v = *(float2*)&acc[p][j];
            lo[j] = v.x; hi[j] = v.y;
        }
        int coL = tx * 8 + 2 * p;
        float* d0 = &g_buf1[((size_t)n * CCH + coL) * HWSZ + (h0 + r) * WWW + w0];
        float* d1 = &g_buf1[((size_t)n * CCH + coL + 1) * HWSZ + (h0 + r) * WWW + w0];
        *(float4*)d0       = make_float4(lo[0], lo[1], lo[2], lo[3]);
        *(float4*)(d0 + 4) = make_float4(lo[4], lo[5], lo[6], lo[7]);
        *(float4*)d1       = make_float4(hi[0], hi[1], hi[2], hi[3]);
        *(float4*)(d1 + 4) = make_float4(hi[4], hi[5], hi[6], hi[7]);
    }
}

// ---- conv2: warp mma.sync s8 (m16n8k32), exact integer arithmetic ---------
#define SMW8_STRIDE 144
#define SMW8_BYTES  (9 * 64 * 144)     // 82944
#define SMA8_OFF    SMW8_BYTES
#define SMA8_IMG    (100 * 144)        // 14400
#define SM2TOT      (SMW8_BYTES + 2 * SMA8_IMG)  // 111744

__global__ void __launch_bounds__(256) k_conv2s()
{
    extern __shared__ char sm[];
    const int t = threadIdx.x, lane = t & 31, warp = t >> 5;
    const int w0 = blockIdx.x * 8, h0 = blockIdx.y * 8;
    const int half = blockIdx.z & 1, n0 = (blockIdx.z >> 1) * 2;

    for (int i = t; i < 4608; i += 256) {
        int row = i >> 3, u = i & 7;
        int kk = row >> 6, coL = row & 63;
        int4 v = ((const int4*)g_w2s8)[(kk * 128 + half * 64 + coL) * 8 + u];
        *(int4*)(sm + row * SMW8_STRIDE + u * 16) = v;
    }
    for (int img = 0; img < 2; img++) {
        for (int i = t; i < 800; i += 256) {
            int px = i >> 3, u = i & 7;
            int py = px / 10, pxx = px - py * 10;
            int h = h0 + py - 1, w = w0 + pxx - 1;
            int4 v = make_int4(0, 0, 0, 0);
            if ((unsigned)h < 56u && (unsigned)w < 56u)
                v = ((const int4*)g_act8)[((n0 + img) * HWSZ + h * WWW + w) * 8 + u];
            *(int4*)(sm + SMA8_OFF + img * SMA8_IMG + py * 1440 + pxx * 144 + u * 16) = v;
        }
    }
    __syncthreads();

    const int mtp  = warp & 3;
    const int cog  = warp >> 2;
    const int colq = lane >> 2;
    const int kq   = (lane & 3) * 4;
    int c[2][4][4] = {};

    #pragma unroll 1
    for (int kk = 0; kk < 9; kk++) {
        const int ky = kk / 3, kx = kk - ky * 3;
        #pragma unroll
        for (int ck = 0; ck < 4; ck++) {
            uint32_t b[4][2];
            #pragma unroll
            for (int nt = 0; nt < 4; nt++) {
                const char* p = sm + (kk * 64 + cog * 32 + nt * 8 + colq) * SMW8_STRIDE
                              + ck * 32 + kq;
                b[nt][0] = *(const uint32_t*)p;
                b[nt][1] = *(const uint32_t*)(p + 16);
            }
            #pragma unroll
            for (int img = 0; img < 2; img++) {
                const char* p = sm + SMA8_OFF + img * SMA8_IMG
                              + (mtp * 2 + ky) * 1440
                              + (colq + kx) * 144 + ck * 32 + kq;
                uint32_t a0 = *(const uint32_t*)p;
                uint32_t a1 = *(const uint32_t*)(p + 1440);
                uint32_t a2 = *(const uint32_t*)(p + 16);
                uint32_t a3 = *(const uint32_t*)(p + 1456);
                #pragma unroll
                for (int nt = 0; nt < 4; nt++)
                    mma16832(c[img][nt], a0, a1, a2, a3, b[nt][0], b[nt][1]);
            }
        }
    }

    const float sc = 1.0f / 225.0f;
    const int m = lane >> 2, nb = (lane & 3) * 2;
    const int h = h0 + mtp * 2, w = w0 + m;
    #pragma unroll
    for (int img = 0; img < 2; img++) {
        #pragma unroll
        for (int nt = 0; nt < 4; nt++) {
            int co = half * 64 + cog * 32 + nt * 8 + nb;
            size_t base = ((size_t)(n0 + img) * CCH + co) * HWSZ;
            const int* cf = c[img][nt];
            g_buf1[base + h * WWW + w]               = (float)cf[0] * sc;
            g_buf1[base + HWSZ + h * WWW + w]        = (float)cf[1] * sc;
            g_buf1[base + (h + 1) * WWW + w]         = (float)cf[2] * sc;
            g_buf1[base + HWSZ + (h + 1) * WWW + w]  = (float)cf[3] * sc;
        }
    }
}

// ---- stats: plain fp32 per-thread partials (fixed order), fp64 combine ----
__global__ void k_statsA() {
    const int c = blockIdx.x, j = blockIdx.y, t = threadIdx.x;
    const size_t base = (size_t)(4 * j) * CHW + (size_t)c * HWSZ;
    float s = 0.f, q = 0.f;
    for (int idx = t; idx < 4 * HWSZ; idx += 256) {
        int n = idx / HWSZ, p = idx - n * HWSZ;
        float v = g_buf1[base + (size_t)n * CHW + p];
        s += v;
        q += v * v;
    }
    __shared__ double ss[256], sq[256];
    ss[t] = (double)s; sq[t] = (double)q;
    __syncthreads();
    for (int o = 128; o > 0; o >>= 1) {
        if (t < o) { ss[t] += ss[t + o]; sq[t] += sq[t + o]; }
        __syncthreads();
    }
    if (t == 0) { g_ps[c * 16 + j] = ss[0]; g_pq[c * 16 + j] = sq[0]; }
}

__global__ void k_statsB(int pass) {
    int c = threadIdx.x;
    double s = 0.0, q = 0.0;
    for (int j = 0; j < 16; j++) { s += g_ps[c * 16 + j]; q += g_pq[c * 16 + j]; }
    double m = s / (double)NHW;
    double var = q / (double)NHW - m * m;
    g_mean[pass * CCH + c] = (float)m;
    g_istd[pass * CCH + c] = (float)(1.0 / sqrt(var + 1e-5));
}

// ---- BN1 + act -> NHWC s8 codes, u32-granular transpose -------------------
__global__ void __launch_bounds__(256) k_bnact8(const float* __restrict__ gamma,
                                                const float* __restrict__ beta) {
    __shared__ uint32_t sm32[32 * 57];             // [c4][p], stride 57
    int n = blockIdx.x / HH, h = blockIdx.x % HH;
    int t = threadIdx.x;
    // phase 1: (c4, p) jobs; pack 4 channels into one u32 in registers
    for (int idx = t; idx < 32 * 56; idx += 256) {
        int c4 = idx / 56, p = idx - c4 * 56;
        uint32_t pack = 0;
        #pragma unroll
        for (int b = 0; b < 4; b++) {
            int c = c4 * 4 + b;
            float v = (g_buf1[(size_t)n * CHW + (size_t)c * HWSZ + h * WWW + p]
                       - g_mean[c]) * g_istd[c];
            v = v * gamma[c] + beta[c];
            float xc = fminf(fmaxf(v, 0.0f), 1.0f);
            pack |= (uint32_t)(int)rintf(xc * 15.0f) << (8 * b);
        }
        sm32[c4 * 57 + p] = pack;
    }
    __syncthreads();
    // phase 2: (p, g) jobs; gather 4 u32 -> uint4, coalesced store
    for (int idx = t; idx < 56 * 8; idx += 256) {
        int p = idx >> 3, g = idx & 7;
        uint4 v = make_uint4(sm32[(g * 4 + 0) * 57 + p], sm32[(g * 4 + 1) * 57 + p],
                             sm32[(g * 4 + 2) * 57 + p], sm32[(g * 4 + 3) * 57 + p]);
        ((uint4*)g_act8)[((size_t)(n * HWSZ + h * WWW + p)) * 8 + g] = v;
    }
}

// ---- BN2 + residual + act -> out (float4 vectorized) ----------------------
__global__ void k_final(const float* __restrict__ x,
                        const float* __restrict__ gamma, const float* __restrict__ beta,
                        float* __restrict__ out) {
    int i4 = blockIdx.x * 256 + threadIdx.x;
    int c = (i4 / (HWSZ / 4)) & (CCH - 1);
    float mean = g_mean[CCH + c], istd = g_istd[CCH + c];
    float ga = gamma[c], be = beta[c];
    float4 y = *(const float4*)&g_buf1[(size_t)i4 * 4];
    float4 xv = *(const float4*)&x[(size_t)i4 * 4];
    float r[4] = {y.x, y.y, y.z, y.w};
    float xr[4] = {xv.x, xv.y, xv.z, xv.w};
    #pragma unroll
    for (int j = 0; j < 4; j++) {
        float xn = (r[j] - mean) * istd;
        float v  = xn * ga + be + xr[j];
        float xc = fminf(fmaxf(v, 0.0f), 1.0f);
        float qq = rintf(xc * 15.0f) / 15.0f;
        r[j] = xc + (qq - xc);
    }
    *(float4*)&out[(size_t)i4 * 4] = make_float4(r[0], r[1], r[2], r[3]);
}

// ---------------------------------------------------------------------------
extern "C" void kernel_launch(void* const* d_in, const int* in_sizes, int n_in,
                              void* d_out, int out_size)
{
    const float* x  = (const float*)d_in[0];
    const float* w1 = (const float*)d_in[1];
    const float* w2 = (const float*)d_in[2];
    const float* g1 = (const float*)d_in[3];
    const float* b1 = (const float*)d_in[4];
    const float* g2 = (const float*)d_in[5];
    const float* b2 = (const float*)d_in[6];
    float* out = (float*)d_out;

    cudaFuncSetAttribute(k_conv2s, cudaFuncAttributeMaxDynamicSharedMemorySize, SM2TOT);

    k_wmaxA<<<dim3(32, 2), 256>>>(w1, w2);
    k_wmaxB<<<1, 32>>>();
    k_wquant<<<dim3(576, 2), 256>>>(w1, w2);

    k_conv1<<<dim3(7, 7, NB), 128>>>(x);                // 4th launch: ncu captures this
    k_statsA<<<dim3(CCH, 16), 256>>>();
    k_statsB<<<1, CCH>>>(0);
    k_bnact8<<<NB * HH, 256>>>(g1, b1);                 // -> g_act8 (NHWC s8)
    k_conv2s<<<dim3(7, 7, 64), 256, SM2TOT>>>();        // s8 mma conv2 -> g_buf1
    k_statsA<<<dim3(CCH, 16), 256>>>();
    k_statsB<<<1, CCH>>>(1);
    k_final<<<TOTAL / 4 / 256, 256>>>(x, g2, b2, out);
}